// round 12
// baseline (speedup 1.0000x reference)
#include <cuda_runtime.h>
#include <cuda_fp16.h>
#include <math.h>
#include <stdint.h>

#define BATCH 4
#define TLEN  4096
#define EDIM  1024
#define DDIM  128
#define MTOT  (BATCH*TLEN)
typedef __half hlf;

// q pre-scale: 1/sqrt(128) * log2(e)
#define QSCALE ((float)(0.08838834764831843 * 1.4426950408889634))

// ---------------- device scratch ----------------
__device__ hlf g_wth[3*DDIM*EDIM];            // Wq/Wk/Wv transposed
__device__ hlf g_wpth[DDIM*DDIM];             // Wp^T hi
__device__ hlf g_wptl[DDIM*DDIM];             // Wp^T lo
__device__ hlf g_qkvh[(size_t)3*MTOT*DDIM];   // planes: q, k, v
__device__ hlf g_oh[(size_t)MTOT*DDIM], g_ol[(size_t)MTOT*DDIM];

// ---------------- helpers ----------------
__device__ __forceinline__ uint32_t su32(const void* p) {
    return (uint32_t)__cvta_generic_to_shared(p);
}
__device__ __forceinline__ void cp16(uint32_t dst, const void* src) {
    asm volatile("cp.async.cg.shared.global [%0], [%1], 16;" :: "r"(dst), "l"(src));
}
#define CP_COMMIT() asm volatile("cp.async.commit_group;" ::: "memory")
template<int N> __device__ __forceinline__ void cp_wait() {
    asm volatile("cp.async.wait_group %0;" :: "n"(N) : "memory");
}
__device__ __forceinline__ uint32_t swz(uint32_t off) {       // 128B rows
    return off ^ ((off >> 3) & 0x70);
}
__device__ __forceinline__ uint32_t sw256(int r, int cb) {    // 256B rows
    return (uint32_t)(r * 256 + (cb ^ ((r & 7) << 4)));
}
#define LDSM4(r, addr) \
    asm volatile("ldmatrix.sync.aligned.m8n8.x4.shared.b16 {%0,%1,%2,%3}, [%4];" \
        : "=r"((r)[0]), "=r"((r)[1]), "=r"((r)[2]), "=r"((r)[3]) : "r"(addr))
#define LDSM4T(r, addr) \
    asm volatile("ldmatrix.sync.aligned.m8n8.x4.trans.shared.b16 {%0,%1,%2,%3}, [%4];" \
        : "=r"((r)[0]), "=r"((r)[1]), "=r"((r)[2]), "=r"((r)[3]) : "r"(addr))
#define MMA16816(d, a, b0, b1) \
    asm volatile("mma.sync.aligned.m16n8k16.row.col.f32.f16.f16.f32 " \
        "{%0,%1,%2,%3}, {%4,%5,%6,%7}, {%8,%9}, {%0,%1,%2,%3};" \
        : "+f"((d)[0]), "+f"((d)[1]), "+f"((d)[2]), "+f"((d)[3]) \
        : "r"((a)[0]), "r"((a)[1]), "r"((a)[2]), "r"((a)[3]), "r"(b0), "r"(b1))

__device__ __forceinline__ uint32_t pk2(float lo, float hi) { // pack {low:lo, high:hi}
    uint32_t r;
    asm("cvt.rn.f16x2.f32 %0, %1, %2;" : "=r"(r) : "f"(hi), "f"(lo));
    return r;
}
__device__ __forceinline__ float lo_f(uint32_t h) {
    __half2 x = *(__half2*)&h; return __low2float(x);
}
__device__ __forceinline__ float hi_f(uint32_t h) {
    __half2 x = *(__half2*)&h; return __high2float(x);
}
__device__ __forceinline__ float ex2(float x) {
    float y; asm("ex2.approx.f32 %0, %1;" : "=f"(y) : "f"(x)); return y;
}

// ---------------- transpose + convert weights ----------------
__global__ __launch_bounds__(256) void convert_w(
    const float* __restrict__ wq, const float* __restrict__ wk,
    const float* __restrict__ wv, const float* __restrict__ wp,
    hlf* __restrict__ wth,
    hlf* __restrict__ wpth, hlf* __restrict__ wptl) {
    int idx = blockIdx.x * 256 + threadIdx.x;
    if (idx < 3 * DDIM * EDIM) {
        int k = idx & (EDIM - 1), n = (idx >> 10) & (DDIM - 1), w = idx >> 17;
        const float* W = (w == 0) ? wq : ((w == 1) ? wk : wv);
        wth[idx] = __float2half_rn(W[(size_t)k * DDIM + n]);
    }
    if (idx < DDIM * DDIM) {
        int k = idx & 127, n = idx >> 7;
        float v = wp[(size_t)k * DDIM + n];
        hlf h = __float2half_rn(v);
        wpth[idx] = h; wptl[idx] = __float2half_rn(v - __half2float(h));
    }
}

// ---------------------------------------------------------------------------
// QKV GEMM, 1-pass fp16, fp32-A converted in-kernel.
// blockIdx.x = plane (0:q +QSCALE, 1:k, 2:v), blockIdx.y = m-block.
// BM=64, BN=128, 256 thr (2m x 4n warps), stage: A 8KB | B 16KB, x2 = 48KB.
// ---------------------------------------------------------------------------
__global__ __launch_bounds__(256, 2) void mm_qkv(
    const float* __restrict__ X, const hlf* __restrict__ Bh0,
    hlf* __restrict__ Ch0) {
    extern __shared__ char smem[];
    const uint32_t sb = su32(smem);
    const int tid = threadIdx.x, lane = tid & 31, warp = tid >> 5;
    const int wm = (warp & 1) * 32, wn = (warp >> 1) * 32;
    const int w = blockIdx.x;
    const int m0 = blockIdx.y * 64;
    const hlf* Bh = Bh0 + (size_t)w * DDIM * EDIM;
    hlf* Ch = Ch0 + (size_t)w * MTOT * DDIM;
    const float oscale = (w == 0) ? QSCALE : 1.f;

    float acc[2][4][4];
#pragma unroll
    for (int i = 0; i < 2; i++)
#pragma unroll
        for (int j = 0; j < 4; j++)
#pragma unroll
            for (int u = 0; u < 4; u++) acc[i][j][u] = 0.f;

    // A staging in registers: 4 float4 per thread (64 rows x 64 cols fp32)
    float4 areg[2][4];
    auto ldgA = [&](int k0, int buf) {
#pragma unroll
        for (int i = 0; i < 4; i++) {
            int u = tid + i * 256;            // 0..1023
            int r = u >> 4, c4 = u & 15;
            areg[buf][i] = *(const float4*)(X + (size_t)(m0 + r) * EDIM + k0 + c4 * 4);
        }
    };
    auto stsA = [&](int st, int buf) {
        uint32_t base = sb + st * 24576;
#pragma unroll
        for (int i = 0; i < 4; i++) {
            int u = tid + i * 256;
            int r = u >> 4, c4 = u & 15;
            float4 v = areg[buf][i];
            uint32_t sw = swz((uint32_t)(r * 128 + c4 * 8));
            uint32_t p0 = pk2(v.x, v.y), p1 = pk2(v.z, v.w);
            asm volatile("st.shared.v2.b32 [%0], {%1, %2};" :: "r"(base + sw),
                         "r"(p0), "r"(p1) : "memory");
        }
    };
    auto prefetchB = [&](int k0, int st) {
        uint32_t base = sb + st * 24576 + 8192;
        for (int u = tid; u < 1024; u += 256) {
            int r = u >> 3, c = u & 7;
            uint32_t sw = swz((uint32_t)(r * 128 + c * 16));
            cp16(base + sw, Bh + (size_t)r * EDIM + k0 + c * 8);
        }
        CP_COMMIT();
    };

    ldgA(0, 0);
    prefetchB(0, 0);
    for (int ck = 0; ck < EDIM / 64; ck++) {
        const int st = ck & 1;
        // issue next-stage global loads first (latency overlap)
        if (ck + 1 < EDIM / 64) {
            ldgA((ck + 1) * 64, (ck + 1) & 1);
            prefetchB((ck + 1) * 64, (ck + 1) & 1);
            cp_wait<1>();
        } else cp_wait<0>();
        // stage-st smem was last read in iter ck-2; syncs of ck-2/ck-1 protect it
        stsA(st, st);
        __syncthreads();
        const uint32_t base = sb + st * 24576;
#pragma unroll
        for (int ks = 0; ks < 4; ks++) {
            const int kb = ks * 16;
            uint32_t a_h[2][4];
#pragma unroll
            for (int mt = 0; mt < 2; mt++) {
                int row = wm + mt * 16 + (lane & 15);
                int colb = (kb + ((lane >> 4) * 8)) * 2;
                LDSM4(a_h[mt], base + swz((uint32_t)(row * 128 + colb)));
            }
            uint32_t b_h[2][4];
#pragma unroll
            for (int np = 0; np < 2; np++) {
                int row = wn + np * 16 + ((lane >> 4) * 8) + (lane & 7);
                int colb = (kb + (((lane >> 3) & 1) * 8)) * 2;
                LDSM4(b_h[np], base + 8192 + swz((uint32_t)(row * 128 + colb)));
            }
#pragma unroll
            for (int mt = 0; mt < 2; mt++)
#pragma unroll
                for (int np = 0; np < 2; np++) {
                    MMA16816(acc[mt][np*2],   a_h[mt], b_h[np][0], b_h[np][1]);
                    MMA16816(acc[mt][np*2+1], a_h[mt], b_h[np][2], b_h[np][3]);
                }
        }
        __syncthreads();
    }

#pragma unroll
    for (int mt = 0; mt < 2; mt++)
#pragma unroll
        for (int j = 0; j < 4; j++) {
            int row = m0 + wm + mt * 16 + (lane >> 2);
            int col = wn + j * 8 + (lane & 3) * 2;
            float v0 = acc[mt][j][0] * oscale, v1 = acc[mt][j][1] * oscale;
            float v2 = acc[mt][j][2] * oscale, v3 = acc[mt][j][3] * oscale;
            *(uint32_t*)(Ch + (size_t)row * 128 + col) = pk2(v0, v1);
            *(uint32_t*)(Ch + (size_t)(row + 8) * 128 + col) = pk2(v2, v3);
        }
}

// ---------------------------------------------------------------------------
// Output projection: out[M,128] = O[M,128] @ Wp. fp16 split 3-pass, fp32 out.
// ---------------------------------------------------------------------------
__global__ __launch_bounds__(256, 2) void mm_out(
    const hlf* __restrict__ Ah, const hlf* __restrict__ Al,
    const hlf* __restrict__ Bh, const hlf* __restrict__ Bl,
    float* __restrict__ C) {
    extern __shared__ char smem[];
    const uint32_t sb = su32(smem);
    const int tid = threadIdx.x, lane = tid & 31, warp = tid >> 5;
    const int wm = (warp & 1) * 32, wn = (warp >> 1) * 32;
    const int m0 = blockIdx.x * 64;
    const int K = DDIM;

    float acc[2][4][4];
#pragma unroll
    for (int i = 0; i < 2; i++)
#pragma unroll
        for (int j = 0; j < 4; j++)
#pragma unroll
            for (int u = 0; u < 4; u++) acc[i][j][u] = 0.f;

    auto prefetch = [&](int k0, int st) {
        uint32_t base = sb + st * 49152;
        for (int u = tid; u < 512; u += 256) {
            int r = u >> 3, c = u & 7;
            uint32_t sw = swz((uint32_t)(r * 128 + c * 16));
            size_t ao = (size_t)(m0 + r) * K + k0 + c * 8;
            cp16(base + sw, Ah + ao);
            cp16(base + 8192 + sw, Al + ao);
        }
        for (int u = tid; u < 1024; u += 256) {
            int r = u >> 3, c = u & 7;
            uint32_t sw = swz((uint32_t)(r * 128 + c * 16));
            size_t bo = (size_t)r * K + k0 + c * 8;
            cp16(base + 16384 + sw, Bh + bo);
            cp16(base + 32768 + sw, Bl + bo);
        }
        CP_COMMIT();
    };

    prefetch(0, 0);
    for (int ck = 0; ck < K / 64; ck++) {
        if (ck + 1 < K / 64) { prefetch((ck + 1) * 64, (ck + 1) & 1); cp_wait<1>(); }
        else cp_wait<0>();
        __syncthreads();
        const uint32_t base = sb + (ck & 1) * 49152;
#pragma unroll
        for (int ks = 0; ks < 4; ks++) {
            const int kb = ks * 16;
            uint32_t a_h[2][4], a_l[2][4];
#pragma unroll
            for (int mt = 0; mt < 2; mt++) {
                int row = wm + mt * 16 + (lane & 15);
                int colb = (kb + ((lane >> 4) * 8)) * 2;
                uint32_t sw = swz((uint32_t)(row * 128 + colb));
                LDSM4(a_h[mt], base + sw);
                LDSM4(a_l[mt], base + 8192 + sw);
            }
            uint32_t b_h[2][4], b_l[2][4];
#pragma unroll
            for (int np = 0; np < 2; np++) {
                int row = wn + np * 16 + ((lane >> 4) * 8) + (lane & 7);
                int colb = (kb + (((lane >> 3) & 1) * 8)) * 2;
                uint32_t sw = swz((uint32_t)(row * 128 + colb));
                LDSM4(b_h[np], base + 16384 + sw);
                LDSM4(b_l[np], base + 32768 + sw);
            }
#pragma unroll
            for (int mt = 0; mt < 2; mt++)
#pragma unroll
                for (int np = 0; np < 2; np++) {
                    MMA16816(acc[mt][np*2],   a_h[mt], b_h[np][0], b_h[np][1]);
                    MMA16816(acc[mt][np*2],   a_l[mt], b_h[np][0], b_h[np][1]);
                    MMA16816(acc[mt][np*2],   a_h[mt], b_l[np][0], b_l[np][1]);
                    MMA16816(acc[mt][np*2+1], a_h[mt], b_h[np][2], b_h[np][3]);
                    MMA16816(acc[mt][np*2+1], a_l[mt], b_h[np][2], b_h[np][3]);
                    MMA16816(acc[mt][np*2+1], a_h[mt], b_l[np][2], b_l[np][3]);
                }
        }
        __syncthreads();
    }

#pragma unroll
    for (int mt = 0; mt < 2; mt++)
#pragma unroll
        for (int j = 0; j < 4; j++) {
            int row = m0 + wm + mt * 16 + (lane >> 2);
            int col = wn + j * 8 + (lane & 3) * 2;
            *(float2*)(C + (size_t)row * 128 + col) =
                make_float2(acc[mt][j][0], acc[mt][j][1]);
            *(float2*)(C + (size_t)(row + 8) * 128 + col) =
                make_float2(acc[mt][j][2], acc[mt][j][3]);
        }
}

// ---------------------------------------------------------------------------
// Flash attention, mma.sync fp16, single-pass QK and PV. Q in registers;
// K and V TRIPLE-buffered (prefetch distance 2). Static grid=256, pair map.
// smem: K0|K1|K2 (48K) + V0|V1|V2 (48K) = 96KB. 2 CTAs/SM (192KB).
// ---------------------------------------------------------------------------
__global__ __launch_bounds__(128, 2) void flash_mma(
    const hlf* __restrict__ qh, const hlf* __restrict__ kh,
    const hlf* __restrict__ vh,
    hlf* __restrict__ oh, hlf* __restrict__ ol) {
    extern __shared__ char smem[];
    const uint32_t sb = su32(smem);
    const uint32_t oK = 0, oV = 49152;           // 3 x 16KB each
    const int tid = threadIdx.x, lane = tid & 31, warp = tid >> 5;
    const int wm = warp * 16;
    const int gr = lane >> 2, j2 = (lane & 3) * 2;

    // pair-balanced mapping: bid & bid+148 co-reside; weights sum ~const
    const int bid = blockIdx.x;
    const int j = (bid < 148) ? bid : (403 - bid);
    const int mt = 63 - (j >> 2), b = j & 3;
    const int m0 = mt * 64, ntiles = mt + 1;
    const size_t boff = (size_t)b * TLEN * DDIM;
    const hlf *Qh = qh + boff, *Kh = kh + boff, *Vh = vh + boff;

    auto loadKV = [&](int n0, int m) {    // 16KB K + 16KB V, one group
        uint32_t kd = sb + oK + m * 16384, vd = sb + oV + m * 16384;
        for (int u = tid; u < 1024; u += 128) {
            int rr = u >> 4, cc = u & 15;
            uint32_t sw = sw256(rr, cc * 16);
            size_t src = (size_t)(n0 + rr) * 128 + cc * 8;
            cp16(kd + sw, Kh + src);
            cp16(vd + sw, Vh + src);
        }
        CP_COMMIT();
    };

    // stage Q into V buf2, then prefetch KV(0)
    for (int u = tid; u < 1024; u += 128) {
        int rr = u >> 4, cc = u & 15;
        cp16(sb + oV + 2 * 16384 + sw256(rr, cc * 16),
             Qh + (size_t)(m0 + rr) * 128 + cc * 8);
    }
    CP_COMMIT();
    loadKV(0, 0);
    cp_wait<1>();          // Q staged (KV0 may be in flight)
    __syncthreads();

    // Q fragments to registers: 8 k-steps x 4 regs
    uint32_t qa[8][4];
#pragma unroll
    for (int ks = 0; ks < 8; ks++) {
        int row = wm + (lane & 15);
        int cb = ks * 32 + ((lane >> 4) << 4);
        LDSM4(qa[ks], sb + oV + 2 * 16384 + sw256(row, cb));
    }

    float o[16][4];
#pragma unroll
    for (int i = 0; i < 16; i++)
#pragma unroll
        for (int u = 0; u < 4; u++) o[i][u] = 0.f;
    float rm[2] = {-INFINITY, -INFINITY}, rl[2] = {0.f, 0.f};

    // prefetch KV(1) (in-bounds for all mt; retired by the loop's waits)
    loadKV(64, 1);

    for (int nt = 0; nt < ntiles; nt++) {
        if (nt + 1 < ntiles) cp_wait<1>(); else cp_wait<0>();  // KV(nt) ready
        __syncthreads();        // all warps done with buf (nt-1)%3 / Q-stage

        if (nt + 2 < ntiles) loadKV((nt + 2) * 64, (nt + 2) % 3);

        const uint32_t kbuf = sb + oK + (nt % 3) * 16384;
        const uint32_t vbuf = sb + oV + (nt % 3) * 16384;

        // ---- S = Q K^T (1-pass fp16) ----
        float s[8][4];
#pragma unroll
        for (int i = 0; i < 8; i++)
#pragma unroll
            for (int u = 0; u < 4; u++) s[i][u] = 0.f;
#pragma unroll
        for (int ks = 0; ks < 8; ks++) {
#pragma unroll
            for (int pr = 0; pr < 4; pr++) {
                uint32_t kb_h[4];
                int row = pr * 16 + ((lane >> 4) << 3) + (lane & 7);
                int cb = ks * 32 + (((lane >> 3) & 1) << 4);
                LDSM4(kb_h, kbuf + sw256(row, cb));
                MMA16816(s[pr*2],   qa[ks], kb_h[0], kb_h[1]);
                MMA16816(s[pr*2+1], qa[ks], kb_h[2], kb_h[3]);
            }
        }

        // ---- causal mask on diagonal tile ----
        if (nt == ntiles - 1) {
#pragma unroll
            for (int nt8 = 0; nt8 < 8; nt8++) {
#pragma unroll
                for (int c = 0; c < 4; c++) {
                    int col = nt8 * 8 + j2 + (c & 1);
                    int row = wm + gr + ((c >> 1) << 3);
                    if (col > row) s[nt8][c] = -1e30f;
                }
            }
        }

        // ---- online softmax ----
        float mx0 = -INFINITY, mx1 = -INFINITY;
#pragma unroll
        for (int i = 0; i < 8; i++) {
            mx0 = fmaxf(mx0, fmaxf(s[i][0], s[i][1]));
            mx1 = fmaxf(mx1, fmaxf(s[i][2], s[i][3]));
        }
        mx0 = fmaxf(mx0, __shfl_xor_sync(0xffffffffu, mx0, 1));
        mx0 = fmaxf(mx0, __shfl_xor_sync(0xffffffffu, mx0, 2));
        mx1 = fmaxf(mx1, __shfl_xor_sync(0xffffffffu, mx1, 1));
        mx1 = fmaxf(mx1, __shfl_xor_sync(0xffffffffu, mx1, 2));
        float mn0 = fmaxf(rm[0], mx0), mn1 = fmaxf(rm[1], mx1);
        float sc0 = ex2(rm[0] - mn0), sc1 = ex2(rm[1] - mn1);
        float sum0 = 0.f, sum1 = 0.f;
#pragma unroll
        for (int i = 0; i < 8; i++) {
            s[i][0] = ex2(s[i][0] - mn0); sum0 += s[i][0];
            s[i][1] = ex2(s[i][1] - mn0); sum0 += s[i][1];
            s[i][2] = ex2(s[i][2] - mn1); sum1 += s[i][2];
            s[i][3] = ex2(s[i][3] - mn1); sum1 += s[i][3];
        }
        sum0 += __shfl_xor_sync(0xffffffffu, sum0, 1);
        sum0 += __shfl_xor_sync(0xffffffffu, sum0, 2);
        sum1 += __shfl_xor_sync(0xffffffffu, sum1, 1);
        sum1 += __shfl_xor_sync(0xffffffffu, sum1, 2);
        rl[0] = rl[0] * sc0 + sum0; rl[1] = rl[1] * sc1 + sum1;
        rm[0] = mn0; rm[1] = mn1;
#pragma unroll
        for (int i = 0; i < 16; i++) {
            o[i][0] *= sc0; o[i][1] *= sc0; o[i][2] *= sc1; o[i][3] *= sc1;
        }

        // ---- pack P to fp16 (A-fragment layout) ----
        uint32_t ph[8][2];
#pragma unroll
        for (int i = 0; i < 8; i++) {
            ph[i][0] = pk2(s[i][0], s[i][1]);
            ph[i][1] = pk2(s[i][2], s[i][3]);
        }

        // ---- O += P V (1-pass fp16) ----
#pragma unroll
        for (int kk = 0; kk < 4; kk++) {
            uint32_t pa[4] = {ph[kk*2][0], ph[kk*2][1], ph[kk*2+1][0], ph[kk*2+1][1]};
#pragma unroll
            for (int dt = 0; dt < 8; dt++) {
                uint32_t vf[4];
                int row = kk * 16 + (lane & 7) + (((lane >> 3) & 1) << 3);
                int cb = dt * 32 + ((lane >> 4) << 4);
                LDSM4T(vf, vbuf + sw256(row, cb));
                MMA16816(o[dt*2],   pa, vf[0], vf[1]);
                MMA16816(o[dt*2+1], pa, vf[2], vf[3]);
            }
        }
    }

    // ---- epilogue: normalize, split to fp16 hi/lo ----
    float inv0 = 1.f / rl[0], inv1 = 1.f / rl[1];
    size_t row0 = (size_t)b * TLEN + m0 + wm + gr;
#pragma unroll
    for (int dt = 0; dt < 16; dt++) {
        int col = dt * 8 + j2;
        float v0 = o[dt][0] * inv0, v1 = o[dt][1] * inv0;
        float v2 = o[dt][2] * inv1, v3 = o[dt][3] * inv1;
        uint32_t h0 = pk2(v0, v1), h1 = pk2(v2, v3);
        *(uint32_t*)(oh + row0 * 128 + col) = h0;
        *(uint32_t*)(ol + row0 * 128 + col) = pk2(v0 - lo_f(h0), v1 - hi_f(h0));
        *(uint32_t*)(oh + (row0 + 8) * 128 + col) = h1;
        *(uint32_t*)(ol + (row0 + 8) * 128 + col) = pk2(v2 - lo_f(h1), v3 - hi_f(h1));
    }
}

// ---------------------------------------------------------------------------
extern "C" void kernel_launch(void* const* d_in, const int* in_sizes, int n_in,
                              void* d_out, int out_size) {
    const float* x  = (const float*)d_in[0];
    const float* Wk = (const float*)d_in[1];
    const float* Wq = (const float*)d_in[2];
    const float* Wv = (const float*)d_in[3];
    const float* Wp = (const float*)d_in[4];
    float* out = (float*)d_out;

    hlf *wth, *wpth, *wptl, *qkvh, *oh, *ol;
    cudaGetSymbolAddress((void**)&wth, g_wth);
    cudaGetSymbolAddress((void**)&wpth, g_wpth); cudaGetSymbolAddress((void**)&wptl, g_wptl);
    cudaGetSymbolAddress((void**)&qkvh, g_qkvh);
    cudaGetSymbolAddress((void**)&oh, g_oh);     cudaGetSymbolAddress((void**)&ol, g_ol);

    const int qkv_smem = 49152;   // 2 stages x 24KB
    const int out_smem = 98304;   // 2 stages x 48KB
    const int fa_smem  = 98304;   // K x3 + V x3 (16KB each)
    cudaFuncSetAttribute(mm_qkv, cudaFuncAttributeMaxDynamicSharedMemorySize, qkv_smem);
    cudaFuncSetAttribute(mm_out, cudaFuncAttributeMaxDynamicSharedMemorySize, out_smem);
    cudaFuncSetAttribute(flash_mma, cudaFuncAttributeMaxDynamicSharedMemorySize, fa_smem);

    convert_w<<<(3 * DDIM * EDIM + 255) / 256, 256>>>(Wq, Wk, Wv, Wp, wth, wpth, wptl);

    // fused QKV (1-pass, fp32-A in-kernel convert): x = plane, y = m-block
    mm_qkv<<<dim3(3, MTOT / 64), 256, qkv_smem>>>(x, wth, qkvh);

    const size_t P = (size_t)MTOT * DDIM;
    flash_mma<<<256, 128, fa_smem>>>(qkvh, qkvh + P, qkvh + 2 * P, oh, ol);

    mm_out<<<MTOT / 64, 256, out_smem>>>(oh, ol, wpth, wptl, out);
}